// round 1
// baseline (speedup 1.0000x reference)
#include <cuda_runtime.h>
#include <cuda_bf16.h>
#include <cstdint>

#define T_DIM 256
#define B_DIM 256
#define H_DIM 512
#define K_DIM 64
#define M_DIM (T_DIM * B_DIM)

// Scratch (device globals: allowed; no allocations anywhere)
__device__ float g_em[(size_t)M_DIM * K_DIM];          // emissions [T,B,K] f32 (16.8 MB)
__device__ __nv_bfloat16 g_Wbf[K_DIM * H_DIM];         // W in bf16 (64 KB)
__device__ float g_diff[B_DIM];                        // per-batch forward-gold

// ---------------------------------------------------------------------------
// Kernel 1: convert W to bf16
// ---------------------------------------------------------------------------
__global__ void convert_w(const float* __restrict__ W) {
    int i = blockIdx.x * blockDim.x + threadIdx.x;
    if (i < K_DIM * H_DIM) g_Wbf[i] = __float2bfloat16(W[i]);
}

__device__ __forceinline__ uint32_t f2bf2(float lo, float hi) {
    uint32_t r;
    asm("cvt.rn.bf16x2.f32 %0, %1, %2;" : "=r"(r) : "f"(hi), "f"(lo));
    return r;
}

// ---------------------------------------------------------------------------
// Kernel 2: emissions GEMM  em[m, k] = sum_h hid[m,h] * W[k,h] + b[k]
// bf16 mma.sync m16n8k16, fp32 accumulate. Block = 256 thr (8 warps),
// each warp computes 16 rows x 64 cols. Grid = 65536/128 = 512 blocks.
// A fragments loaded straight from global f32 (float2 -> bf16x2), W from
// the bf16 scratch (L1/L2 resident, only 64 KB).
// ---------------------------------------------------------------------------
__global__ __launch_bounds__(256) void emis_gemm(const float* __restrict__ hid,
                                                 const float* __restrict__ bias) {
    int warp = threadIdx.x >> 5;
    int lane = threadIdx.x & 31;
    int g  = lane >> 2;   // 0..7
    int tg = lane & 3;    // 0..3
    int row0 = blockIdx.x * 128 + warp * 16;

    const float* a0p = hid + (size_t)(row0 + g) * H_DIM;
    const float* a1p = hid + (size_t)(row0 + g + 8) * H_DIM;

    float acc[8][4];
#pragma unroll
    for (int nt = 0; nt < 8; nt++)
#pragma unroll
        for (int q = 0; q < 4; q++) acc[nt][q] = 0.f;

#pragma unroll 4
    for (int k0 = 0; k0 < H_DIM; k0 += 16) {
        float2 v0 = *(const float2*)(a0p + k0 + tg * 2);
        float2 v1 = *(const float2*)(a1p + k0 + tg * 2);
        float2 v2 = *(const float2*)(a0p + k0 + tg * 2 + 8);
        float2 v3 = *(const float2*)(a1p + k0 + tg * 2 + 8);
        uint32_t a0 = f2bf2(v0.x, v0.y);
        uint32_t a1 = f2bf2(v1.x, v1.y);
        uint32_t a2 = f2bf2(v2.x, v2.y);
        uint32_t a3 = f2bf2(v3.x, v3.y);
#pragma unroll
        for (int nt = 0; nt < 8; nt++) {
            int n = nt * 8 + g;
            const uint32_t* wrow = (const uint32_t*)(g_Wbf + n * H_DIM + k0);
            uint32_t b0 = wrow[tg];       // k = k0 + tg*2, +1
            uint32_t b1 = wrow[tg + 4];   // k = k0 + 8 + tg*2, +1
            asm volatile(
                "mma.sync.aligned.m16n8k16.row.col.f32.bf16.bf16.f32 "
                "{%0,%1,%2,%3}, {%4,%5,%6,%7}, {%8,%9}, {%0,%1,%2,%3};"
                : "+f"(acc[nt][0]), "+f"(acc[nt][1]), "+f"(acc[nt][2]), "+f"(acc[nt][3])
                : "r"(a0), "r"(a1), "r"(a2), "r"(a3), "r"(b0), "r"(b1));
        }
    }

    int r0 = row0 + g, r1 = row0 + g + 8;
#pragma unroll
    for (int nt = 0; nt < 8; nt++) {
        int c = nt * 8 + tg * 2;
        float b0v = bias[c], b1v = bias[c + 1];
        float2 o;
        o.x = acc[nt][0] + b0v; o.y = acc[nt][1] + b1v;
        *(float2*)(g_em + (size_t)r0 * K_DIM + c) = o;
        o.x = acc[nt][2] + b0v; o.y = acc[nt][3] + b1v;
        *(float2*)(g_em + (size_t)r1 * K_DIM + c) = o;
    }
}

// ---------------------------------------------------------------------------
// Kernel 3: CRF forward DP + gold score. One block per batch b, 256 threads.
// Thread (j = tid&63, h = tid>>6) holds exp(transition[j, h*16 .. h*16+15]).
// Recurrence in shifted form: abar_j = alpha_j - alpha_0, C = alpha_0.
//   p_j = exp(abar_j); s_j = sum_i p_i * expT[j,i]
//   alpha'_j = C + log(s_j) + em'_j  ->  abar' = (log s_j - log s_0) + (em'_j - em'_0)
//   C' = C + log s_0 + em'_0
// Only 2 __syncthreads per timestep; em for t+1 prefetched.
// ---------------------------------------------------------------------------
__global__ __launch_bounds__(256) void crf_dp(const int* __restrict__ lens,
                                              const int* __restrict__ tags,
                                              const float* __restrict__ trans,
                                              const float* __restrict__ begin,
                                              const float* __restrict__ endt) {
    int b = blockIdx.x;
    int tid = threadIdx.x;
    int j = tid & 63;
    int h = tid >> 6;         // 0..3
    int lane = tid & 31;
    int wid = tid >> 5;
    int len = lens[b];

    __shared__ __align__(16) float sm_p[64];
    __shared__ float sm_part[256];
    __shared__ float sm_red[8];
    __shared__ float sm_gold;

    // ---- gold path score: fully parallel segment sum over t ----
    float gpart = 0.f;
    for (int t = tid; t < len; t += 256) {
        int tag = tags[t * B_DIM + b];
        float inc;
        if (t == 0) inc = begin[tag];
        else        inc = trans[tag * K_DIM + tags[(t - 1) * B_DIM + b]];
        inc += g_em[((size_t)t * B_DIM + b) * K_DIM + tag];
        gpart += inc;
    }
#pragma unroll
    for (int o = 16; o; o >>= 1) gpart += __shfl_down_sync(0xffffffffu, gpart, o);
    if (lane == 0) sm_red[wid] = gpart;
    __syncthreads();
    if (tid == 0) {
        float gsum = 0.f;
#pragma unroll
        for (int w = 0; w < 8; w++) gsum += sm_red[w];
        gsum += endt[tags[(len - 1) * B_DIM + b]];
        sm_gold = gsum;
    }

    // ---- exp(transition) slice into registers ----
    float eT[16];
    {
        const float* tr = trans + j * K_DIM + h * 16;
#pragma unroll
        for (int ii = 0; ii < 16; ii++) eT[ii] = expf(tr[ii]);
    }

    // ---- t = 0 ----
    float a_j = begin[j] + g_em[(size_t)b * K_DIM + j];
    float a_0 = begin[0] + g_em[(size_t)b * K_DIM];
    float abar = a_j - a_0;
    float C = a_0;

    float em_nj = 0.f, em_n0 = 0.f;
    if (len > 1) {
        size_t base = ((size_t)B_DIM + b) * K_DIM;
        em_nj = g_em[base + j];
        em_n0 = g_em[base];
    }
    __syncthreads();  // sm_gold visible; sm_red free for reuse

    // ---- serial DP over time ----
    for (int t = 1; t < len; t++) {
        // prefetch em for t+1
        float em_pj = 0.f, em_p0 = 0.f;
        if (t + 1 < len) {
            size_t base = ((size_t)(t + 1) * B_DIM + b) * K_DIM;
            em_pj = g_em[base + j];
            em_p0 = g_em[base];
        }
        if (h == 0) sm_p[j] = expf(abar);
        __syncthreads();

        const float4* p4 = (const float4*)(sm_p + h * 16);
        float4 q0 = p4[0], q1 = p4[1], q2 = p4[2], q3 = p4[3];
        float s0 = q0.x * eT[0]  + q0.y * eT[1]  + q0.z * eT[2]  + q0.w * eT[3];
        float s1 = q1.x * eT[4]  + q1.y * eT[5]  + q1.z * eT[6]  + q1.w * eT[7];
        float s2 = q2.x * eT[8]  + q2.y * eT[9]  + q2.z * eT[10] + q2.w * eT[11];
        float s3 = q3.x * eT[12] + q3.y * eT[13] + q3.z * eT[14] + q3.w * eT[15];
        sm_part[h * 64 + j] = (s0 + s1) + (s2 + s3);
        __syncthreads();

        float sj = (sm_part[j] + sm_part[64 + j]) + (sm_part[128 + j] + sm_part[192 + j]);
        float s0tot = (sm_part[0] + sm_part[64]) + (sm_part[128] + sm_part[192]);
        float lj = logf(sj), l0 = logf(s0tot);
        abar = (lj - l0) + (em_nj - em_n0);
        C += l0 + em_n0;
        em_nj = em_pj; em_n0 = em_p0;
    }

    // ---- forward score = C + logsumexp_j(abar_j + end_j) ----
    float val = abar + endt[j];
    if (h == 0) {
        float m = val;
#pragma unroll
        for (int o = 16; o; o >>= 1) m = fmaxf(m, __shfl_xor_sync(0xffffffffu, m, o));
        if (lane == 0) sm_red[wid] = m;  // wid 0,1
    }
    __syncthreads();
    float mm = fmaxf(sm_red[0], sm_red[1]);
    if (h == 0) {
        float e = expf(val - mm);
#pragma unroll
        for (int o = 16; o; o >>= 1) e += __shfl_down_sync(0xffffffffu, e, o);
        if (lane == 0) sm_red[4 + wid] = e;
    }
    __syncthreads();
    if (tid == 0) {
        float fwd = C + mm + logf(sm_red[4] + sm_red[5]);
        g_diff[b] = fwd - sm_gold;
    }
}

// ---------------------------------------------------------------------------
// Kernel 4: deterministic final reduction of 256 per-batch diffs
// ---------------------------------------------------------------------------
__global__ void final_reduce(float* __restrict__ out) {
    __shared__ float s[256];
    int t = threadIdx.x;
    s[t] = g_diff[t];
    __syncthreads();
    for (int k = 128; k > 0; k >>= 1) {
        if (t < k) s[t] += s[t + k];
        __syncthreads();
    }
    if (t == 0) out[0] = s[0];
}

// ---------------------------------------------------------------------------
extern "C" void kernel_launch(void* const* d_in, const int* in_sizes, int n_in,
                              void* d_out, int out_size) {
    const float* hiddens = (const float*)d_in[0];   // [T,B,H] f32
    const int*   lens    = (const int*)d_in[1];     // [B]
    const int*   tags    = (const int*)d_in[2];     // [T,B]
    const float* W       = (const float*)d_in[3];   // [K,H]
    const float* bias    = (const float*)d_in[4];   // [K]
    const float* begin   = (const float*)d_in[5];   // [K]
    const float* trans   = (const float*)d_in[6];   // [K,K]
    const float* endt    = (const float*)d_in[7];   // [K]
    float* out = (float*)d_out;

    convert_w<<<(K_DIM * H_DIM + 255) / 256, 256>>>(W);
    emis_gemm<<<M_DIM / 128, 256>>>(hiddens, bias);
    crf_dp<<<B_DIM, 256>>>(lens, tags, trans, begin, endt);
    final_reduce<<<1, 256>>>(out);
}

// round 2
// speedup vs baseline: 1.5211x; 1.5211x over previous
#include <cuda_runtime.h>
#include <cuda_bf16.h>
#include <cstdint>

#define T_DIM 256
#define B_DIM 256
#define H_DIM 512
#define K_DIM 64
#define M_DIM (T_DIM * B_DIM)

// Scratch (device globals; no allocations anywhere)
__device__ float g_em[(size_t)M_DIM * K_DIM];   // emissions [T,B,K] f32
__device__ float g_diff[B_DIM];                 // per-batch forward - gold

__device__ __forceinline__ uint32_t f2bf2(float lo, float hi) {
    uint32_t r;
    asm("cvt.rn.bf16x2.f32 %0, %1, %2;" : "=r"(r) : "f"(hi), "f"(lo));
    return r;
}

// ---------------------------------------------------------------------------
// Kernel 1: emissions GEMM  em[m,k] = sum_h hid[m,h] * W[k,h] + b[k]
// W staged per-block into SMEM as bf16x2 with XOR swizzle (conflict-free LDS).
// bf16 mma.sync m16n8k16, fp32 accum. 256 thr, warp = 16 rows x 64 cols.
// ---------------------------------------------------------------------------
extern __shared__ uint32_t sW[];   // [256][64] uint32 = 64 KB dynamic

__global__ __launch_bounds__(256) void emis_gemm(const float* __restrict__ hid,
                                                 const float* __restrict__ W,
                                                 const float* __restrict__ bias) {
    int tid = threadIdx.x;

    // Stage W: word w = (n*256 + h2) of bf16x2-packed W[n][h].
    // smem index: h2*64 + (n ^ ((h2&3)<<3))  -> conflict-free reads in mainloop.
    for (int w = tid; w < (K_DIM * H_DIM) / 2; w += 256) {
        float2 v = ((const float2*)W)[w];
        int n  = w >> 8;
        int h2 = w & 255;
        sW[h2 * 64 + (n ^ ((h2 & 3) << 3))] = f2bf2(v.x, v.y);
    }
    __syncthreads();

    int warp = tid >> 5;
    int lane = tid & 31;
    int g  = lane >> 2;   // 0..7
    int tg = lane & 3;    // 0..3
    int row0 = blockIdx.x * 128 + warp * 16;

    const float* a0p = hid + (size_t)(row0 + g) * H_DIM;
    const float* a1p = hid + (size_t)(row0 + g + 8) * H_DIM;

    float acc[8][4];
#pragma unroll
    for (int nt = 0; nt < 8; nt++)
#pragma unroll
        for (int q = 0; q < 4; q++) acc[nt][q] = 0.f;

#pragma unroll 2
    for (int k0 = 0; k0 < H_DIM; k0 += 16) {
        float2 v0 = *(const float2*)(a0p + k0 + tg * 2);
        float2 v1 = *(const float2*)(a1p + k0 + tg * 2);
        float2 v2 = *(const float2*)(a0p + k0 + tg * 2 + 8);
        float2 v3 = *(const float2*)(a1p + k0 + tg * 2 + 8);
        uint32_t a0 = f2bf2(v0.x, v0.y);
        uint32_t a1 = f2bf2(v1.x, v1.y);
        uint32_t a2 = f2bf2(v2.x, v2.y);
        uint32_t a3 = f2bf2(v3.x, v3.y);
        int rbase = (k0 >> 1) * 64;
#pragma unroll
        for (int nt = 0; nt < 8; nt++) {
            // n ^ (tg<<3) = (nt^tg)*8 + g   (both b0 and b1 rows share h2&3 == tg)
            int nx = ((nt ^ tg) << 3) + g;
            uint32_t b0 = sW[rbase + tg * 64 + nx];
            uint32_t b1 = sW[rbase + (tg + 4) * 64 + nx];
            asm volatile(
                "mma.sync.aligned.m16n8k16.row.col.f32.bf16.bf16.f32 "
                "{%0,%1,%2,%3}, {%4,%5,%6,%7}, {%8,%9}, {%0,%1,%2,%3};"
                : "+f"(acc[nt][0]), "+f"(acc[nt][1]), "+f"(acc[nt][2]), "+f"(acc[nt][3])
                : "r"(a0), "r"(a1), "r"(a2), "r"(a3), "r"(b0), "r"(b1));
        }
    }

    int r0 = row0 + g, r1 = row0 + g + 8;
#pragma unroll
    for (int nt = 0; nt < 8; nt++) {
        int c = nt * 8 + tg * 2;
        float b0v = bias[c], b1v = bias[c + 1];
        float2 o;
        o.x = acc[nt][0] + b0v; o.y = acc[nt][1] + b1v;
        *(float2*)(g_em + (size_t)r0 * K_DIM + c) = o;
        o.x = acc[nt][2] + b0v; o.y = acc[nt][3] + b1v;
        *(float2*)(g_em + (size_t)r1 * K_DIM + c) = o;
    }
}

// ---------------------------------------------------------------------------
// Kernel 2: CRF forward DP + gold score.
// 2 batches per block (128 thr), each batch = 64 threads in its own named-
// barrier group -> 128 blocks = single wave on 148 SMs.
// Thread j holds exp(trans[j][0..63]) packed as f32x2; one sync per timestep:
//   state: a = alpha_j(t) - alpha_0(t-1), C = alpha_0(t-1)
//   publish p_j = exp(a), d = a_0 in one barrier (double-buffered)
//   s_j = sum_i p_i * eT[j][i];  a' = log(s_j) + em[t+1][j] - d;  C += d
// ---------------------------------------------------------------------------
#define FMA2(acc, a, b) \
    asm("fma.rn.f32x2 %0, %1, %2, %3;" : "=l"(acc) : "l"(a), "l"(b), "l"(acc))

__global__ __launch_bounds__(128) void crf_dp(const int* __restrict__ lens,
                                              const int* __restrict__ tags,
                                              const float* __restrict__ trans,
                                              const float* __restrict__ begin,
                                              const float* __restrict__ endt) {
    int tid  = threadIdx.x;
    int gid  = tid >> 6;          // 0 or 1: batch group within block
    int j    = tid & 63;
    int lane = tid & 31;
    int wing = (tid >> 5) & 1;    // warp within group
    int b    = blockIdx.x * 2 + gid;
    int len  = lens[b];
    int barid = gid + 1;

    __shared__ __align__(16) float sm_p[2][2][64];
    __shared__ float sm_d[2][2];
    __shared__ float sm_g[2][2];

#define GBAR() asm volatile("bar.sync %0, 64;" :: "r"(barid) : "memory")

    // ---- gold path score (parallel segment sum over t) ----
    float gpart = 0.f;
    for (int t = j; t < len; t += 64) {
        int tag = tags[t * B_DIM + b];
        float inc;
        if (t == 0) inc = begin[tag];
        else        inc = trans[tag * K_DIM + tags[(t - 1) * B_DIM + b]];
        inc += g_em[((size_t)t * B_DIM + b) * K_DIM + tag];
        gpart += inc;
    }
#pragma unroll
    for (int o = 16; o; o >>= 1) gpart += __shfl_down_sync(0xffffffffu, gpart, o);
    if (lane == 0) sm_g[gid][wing] = gpart;
    GBAR();
    float goldv = 0.f;
    if (j == 0)
        goldv = sm_g[gid][0] + sm_g[gid][1] + endt[tags[(len - 1) * B_DIM + b]];
    GBAR();   // sm_g free for reuse at the end

    // ---- exp(transition) row j, packed f32x2 ----
    unsigned long long eT2[32];
    {
        const float4* tr4 = (const float4*)(trans + j * K_DIM);
#pragma unroll
        for (int q = 0; q < 16; q++) {
            float4 v = tr4[q];
            float e0 = __expf(v.x), e1 = __expf(v.y);
            float e2 = __expf(v.z), e3 = __expf(v.w);
            asm("mov.b64 %0, {%1,%2};" : "=l"(eT2[2*q])   : "f"(e0), "f"(e1));
            asm("mov.b64 %0, {%1,%2};" : "=l"(eT2[2*q+1]) : "f"(e2), "f"(e3));
        }
    }

    // ---- t = 0 state ----
    float a = begin[j] + g_em[(size_t)b * K_DIM + j];   // alpha_j(0), C=0
    float C = 0.f;
    float em_n = (len > 1) ? g_em[((size_t)B_DIM + b) * K_DIM + j] : 0.f;

    // ---- serial DP: len-1 steps, ONE named barrier each ----
    for (int t = 0; t < len - 1; t++) {
        int buf = t & 1;
        sm_p[gid][buf][j] = __expf(a);
        if (j == 0) sm_d[gid][buf] = a;
        GBAR();

        // prefetch em for t+2 (consumed next iteration)
        float em_p = 0.f;
        if (t + 2 < len)
            em_p = g_em[((size_t)(t + 2) * B_DIM + b) * K_DIM + j];

        float d = sm_d[gid][buf];
        const ulonglong2* pp = (const ulonglong2*)sm_p[gid][buf];
        unsigned long long acc0 = 0, acc1 = 0, acc2 = 0, acc3 = 0;
#pragma unroll
        for (int q = 0; q < 16; q += 2) {
            ulonglong2 va = pp[q];
            ulonglong2 vb = pp[q + 1];
            FMA2(acc0, va.x, eT2[2*q]);
            FMA2(acc1, va.y, eT2[2*q+1]);
            FMA2(acc2, vb.x, eT2[2*q+2]);
            FMA2(acc3, vb.y, eT2[2*q+3]);
        }
        float s;
        {
            float l0, h0, l1, h1, l2, h2, l3, h3;
            asm("mov.b64 {%0,%1}, %2;" : "=f"(l0), "=f"(h0) : "l"(acc0));
            asm("mov.b64 {%0,%1}, %2;" : "=f"(l1), "=f"(h1) : "l"(acc1));
            asm("mov.b64 {%0,%1}, %2;" : "=f"(l2), "=f"(h2) : "l"(acc2));
            asm("mov.b64 {%0,%1}, %2;" : "=f"(l3), "=f"(h3) : "l"(acc3));
            s = ((l0 + h0) + (l1 + h1)) + ((l2 + h2) + (l3 + h3));
        }
        C += d;
        a = __logf(s) + em_n - d;
        em_n = em_p;
    }

    // ---- forward = C + log(sum_j exp(a_j + end_j))  (shift-free: |a|<~40) ----
    float e = __expf(a + endt[j]);
#pragma unroll
    for (int o = 16; o; o >>= 1) e += __shfl_down_sync(0xffffffffu, e, o);
    if (lane == 0) sm_g[gid][wing] = e;
    GBAR();
    if (j == 0) {
        float fwd = C + __logf(sm_g[gid][0] + sm_g[gid][1]);
        g_diff[b] = fwd - goldv;
    }
#undef GBAR
}

// ---------------------------------------------------------------------------
// Kernel 3: deterministic final reduction
// ---------------------------------------------------------------------------
__global__ void final_reduce(float* __restrict__ out) {
    __shared__ float s[256];
    int t = threadIdx.x;
    s[t] = g_diff[t];
    __syncthreads();
    for (int k = 128; k > 0; k >>= 1) {
        if (t < k) s[t] += s[t + k];
        __syncthreads();
    }
    if (t == 0) out[0] = s[0];
}

// ---------------------------------------------------------------------------
extern "C" void kernel_launch(void* const* d_in, const int* in_sizes, int n_in,
                              void* d_out, int out_size) {
    const float* hiddens = (const float*)d_in[0];   // [T,B,H] f32
    const int*   lens    = (const int*)d_in[1];     // [B]
    const int*   tags    = (const int*)d_in[2];     // [T,B]
    const float* W       = (const float*)d_in[3];   // [K,H]
    const float* bias    = (const float*)d_in[4];   // [K]
    const float* begin   = (const float*)d_in[5];   // [K]
    const float* trans   = (const float*)d_in[6];   // [K,K]
    const float* endt    = (const float*)d_in[7];   // [K]
    float* out = (float*)d_out;

    cudaFuncSetAttribute(emis_gemm, cudaFuncAttributeMaxDynamicSharedMemorySize, 65536);

    emis_gemm<<<M_DIM / 128, 256, 65536>>>(hiddens, W, bias);
    crf_dp<<<B_DIM / 2, 128>>>(lens, tags, trans, begin, endt);
    final_reduce<<<1, 256>>>(out);
}